// round 13
// baseline (speedup 1.0000x reference)
#include <cuda_runtime.h>
#include <cuda_fp16.h>

// Problem constants
#define NN 50000
#define DD 64
#define HH 8
#define HD 512          // H * D
#define EE 400000
#define ET (EE + NN)    // edges + self loops
#define LN_EPS 1e-5f
#define NEG 0.2f
#define GNT 16          // nodes per GEMM block tile
#define XSP 20          // padded smem row stride (floats); 80B, 16B-aligned rows
#define NSB 98          // scan blocks

typedef unsigned long long u64;

// ---------------- scratch (static device memory) ---------------------------
__device__ __align__(16) float  g_xl[(size_t)NN * HD];  // 102.4 MB (fp32: no cvt in edge loop)
__device__ __align__(16) __half g_xr[(size_t)NN * HD];  // 51.2 MB
__device__ __align__(16) float  g_xa[NN * DD];
__device__ __align__(16) float  g_xb[NN * DD];
__device__ int g_rowptr[NN + 1];
__device__ int g_cnt[NN];
__device__ int g_srcs[ET];
__device__ int g_is64;
__device__ int g_bsum[NSB];
__device__ int g_boff[NSB];

// ---------------- packed f32x2 helpers --------------------------------------
__device__ __forceinline__ u64 pk2(float lo, float hi) {
    u64 r;
    asm("mov.b64 %0, {%1, %2};" : "=l"(r) : "f"(lo), "f"(hi));
    return r;
}
__device__ __forceinline__ void upk2(u64 v, float& lo, float& hi) {
    asm("mov.b64 {%0, %1}, %2;" : "=f"(lo), "=f"(hi) : "l"(v));
}
__device__ __forceinline__ void fma2(u64& d, u64 a, u64 b) {   // d += a*b
    asm("fma.rn.f32x2 %0, %1, %2, %0;" : "+l"(d) : "l"(a), "l"(b));
}
__device__ __forceinline__ u64 add2(u64 a, u64 b) {
    u64 r;
    asm("add.rn.f32x2 %0, %1, %2;" : "=l"(r) : "l"(a), "l"(b));
    return r;
}
__device__ __forceinline__ u64 mul2(u64 a, u64 b) {
    u64 r;
    asm("mul.rn.f32x2 %0, %1, %2;" : "=l"(r) : "l"(a), "l"(b));
    return r;
}
__device__ __forceinline__ float lrelu(float x) { return x > 0.f ? x : NEG * x; }
__device__ __forceinline__ int edge_at(const void* ei, int i, int is64) {
    if (is64) return (int)((const long long*)ei)[i];
    return ((const int*)ei)[i];
}

// ---------------- CSR build ------------------------------------------------
__global__ void zero_detect_kernel(const void* ei) {
    int i = blockIdx.x * blockDim.x + threadIdx.x;
    if (i < NN) g_cnt[i] = 0;
    if (i == 0) {
        const u64* p = (const u64*)ei;
        int is64 = 1;
        for (int k = 0; k < 16; k++)
            if (p[k] >= (u64)NN) { is64 = 0; break; }
        g_is64 = is64;
    }
}

__global__ void count_kernel(const void* __restrict__ ei) {
    int e = blockIdx.x * blockDim.x + threadIdx.x;
    if (e >= ET) return;
    int is64 = g_is64;
    int dst = (e < EE) ? edge_at(ei, EE + e, is64) : (e - EE);
    atomicAdd(&g_cnt[dst], 1);
}

__global__ void scan1_kernel() {
    __shared__ int ws[16];
    int tid = threadIdx.x, lane = tid & 31, w = tid >> 5;
    int i = blockIdx.x * 512 + tid;
    int v = (i < NN) ? g_cnt[i] : 0;
    int x = v;
#pragma unroll
    for (int off = 1; off < 32; off <<= 1) {
        int t = __shfl_up_sync(0xffffffffu, x, off);
        if (lane >= off) x += t;
    }
    if (lane == 31) ws[w] = x;
    __syncthreads();
    if (w == 0) {
        int y = (lane < 16) ? ws[lane] : 0;
#pragma unroll
        for (int off = 1; off < 16; off <<= 1) {
            int t = __shfl_up_sync(0xffffffffu, y, off);
            if (lane >= off) y += t;
        }
        if (lane < 16) ws[lane] = y;
    }
    __syncthreads();
    int incl = x + (w ? ws[w - 1] : 0);
    if (i < NN) g_rowptr[i + 1] = incl;
    if (tid == 511) g_bsum[blockIdx.x] = incl;
}

__global__ void scan2_kernel() {
    __shared__ int ws[4];
    int t = threadIdx.x, lane = t & 31, w = t >> 5;
    int v = (t < NSB) ? g_bsum[t] : 0;
    int x = v;
#pragma unroll
    for (int off = 1; off < 32; off <<= 1) {
        int u = __shfl_up_sync(0xffffffffu, x, off);
        if (lane >= off) x += u;
    }
    if (lane == 31) ws[w] = x;
    __syncthreads();
    if (t == 0) {
        int r = 0;
#pragma unroll
        for (int q = 0; q < 4; q++) { int s = ws[q]; ws[q] = r; r += s; }
        g_rowptr[0] = 0;
    }
    __syncthreads();
    if (t < NSB) g_boff[t] = x - v + ws[w];
}

__global__ void scan3_kernel() {   // add offsets + re-zero cnt
    int i = blockIdx.x * 512 + threadIdx.x;
    if (i < NN) {
        g_rowptr[i + 1] += g_boff[blockIdx.x];
        g_cnt[i] = 0;
    }
}

__global__ void scatter_kernel(const void* __restrict__ ei) {
    int e = blockIdx.x * blockDim.x + threadIdx.x;
    if (e >= ET) return;
    int is64 = g_is64;
    int src, dst;
    if (e < EE) { src = edge_at(ei, e, is64); dst = edge_at(ei, EE + e, is64); }
    else        { src = dst = e - EE; }
    int pos = g_rowptr[dst] + atomicAdd(&g_cnt[dst], 1);
    g_srcs[pos] = src;
}

// ---------------- GEMM: g_xl(f32)=xin@Wl ; g_xr(fp16)=xin@Wr ---------------
// 256 threads, 16 nodes/block. LDS.128 loads (4/k) instead of 8 LDS.64.
__global__ void __launch_bounds__(256)
gemm_kernel(const float* __restrict__ xin,
            const float* __restrict__ Wl, const float* __restrict__ Wr,
            int layer) {
    __shared__ __align__(16) float xs[DD][XSP];
    int tid = threadIdx.x;
    int n0  = blockIdx.x * GNT;
    int side = blockIdx.y;
    const float* W = (side ? Wr : Wl) + (size_t)layer * DD * HD;

    for (int i = tid; i < GNT * DD; i += 256) {
        int n = i >> 6, k = i & 63;
        xs[k][n] = xin[(n0 + n) * DD + k];
    }
    __syncthreads();

    int j0 = tid, j1 = tid + 256;
    u64 acc0[GNT / 2], acc1[GNT / 2];
#pragma unroll
    for (int p = 0; p < GNT / 2; p++) { acc0[p] = 0ull; acc1[p] = 0ull; }

#pragma unroll 4
    for (int k = 0; k < DD; k++) {
        float w0 = __ldg(&W[k * HD + j0]);
        float w1 = __ldg(&W[k * HD + j1]);
        u64 w02 = pk2(w0, w0);
        u64 w12 = pk2(w1, w1);
        ulonglong2 q0 = *reinterpret_cast<const ulonglong2*>(&xs[k][0]);
        ulonglong2 q1 = *reinterpret_cast<const ulonglong2*>(&xs[k][4]);
        ulonglong2 q2 = *reinterpret_cast<const ulonglong2*>(&xs[k][8]);
        ulonglong2 q3 = *reinterpret_cast<const ulonglong2*>(&xs[k][12]);
        fma2(acc0[0], q0.x, w02); fma2(acc1[0], q0.x, w12);
        fma2(acc0[1], q0.y, w02); fma2(acc1[1], q0.y, w12);
        fma2(acc0[2], q1.x, w02); fma2(acc1[2], q1.x, w12);
        fma2(acc0[3], q1.y, w02); fma2(acc1[3], q1.y, w12);
        fma2(acc0[4], q2.x, w02); fma2(acc1[4], q2.x, w12);
        fma2(acc0[5], q2.y, w02); fma2(acc1[5], q2.y, w12);
        fma2(acc0[6], q3.x, w02); fma2(acc1[6], q3.x, w12);
        fma2(acc0[7], q3.y, w02); fma2(acc1[7], q3.y, w12);
    }

    if (side == 0) {
#pragma unroll
        for (int p = 0; p < GNT / 2; p++) {
            float a, b;
            upk2(acc0[p], a, b);
            g_xl[(size_t)(n0 + 2 * p) * HD + j0]     = a;
            g_xl[(size_t)(n0 + 2 * p + 1) * HD + j0] = b;
            upk2(acc1[p], a, b);
            g_xl[(size_t)(n0 + 2 * p) * HD + j1]     = a;
            g_xl[(size_t)(n0 + 2 * p + 1) * HD + j1] = b;
        }
    } else {
#pragma unroll
        for (int p = 0; p < GNT / 2; p++) {
            float a, b;
            upk2(acc0[p], a, b);
            g_xr[(size_t)(n0 + 2 * p) * HD + j0]     = __float2half_rn(a);
            g_xr[(size_t)(n0 + 2 * p + 1) * HD + j0] = __float2half_rn(b);
            upk2(acc1[p], a, b);
            g_xr[(size_t)(n0 + 2 * p) * HD + j1]     = __float2half_rn(a);
            g_xr[(size_t)(n0 + 2 * p + 1) * HD + j1] = __float2half_rn(b);
        }
    }
}

// ---------------- fused edge attention + aggregation + node epilogue -------
// WARP-per-node; lane owns 16 channels as 8 packed f32x2 pairs.
// lrelu via 0.6x + 0.4|x| (branch-free, abs = 64-bit AND on the pair).
// No-max softmax (logits bounded << 88). All channel math in f32x2.
__global__ void __launch_bounds__(256)
edge_node_kernel(const float* __restrict__ att, const float* __restrict__ bb,
                 const float* __restrict__ gam, const float* __restrict__ bet,
                 const float* __restrict__ xprev, float* __restrict__ xnext,
                 int layer) {
    int lane = threadIdx.x & 31;
    int node = blockIdx.x * 8 + (threadIdx.x >> 5);   // 50000 = 6250*8

    const u64 ABS2 = 0x7FFFFFFF7FFFFFFFull;
    const u64 C06  = pk2(0.6f, 0.6f);
    const u64 C04  = pk2(0.4f, 0.4f);

    // xr (fp16) -> packed f32x2 pairs
    u64 xr2[8];
    {
        uint4 ha = reinterpret_cast<const uint4*>(g_xr + (size_t)node * HD + lane * 16)[0];
        uint4 hb = reinterpret_cast<const uint4*>(g_xr + (size_t)node * HD + lane * 16)[1];
        const unsigned* u = &ha.x;
#pragma unroll
        for (int i = 0; i < 4; i++) {
            float2 t = __half22float2(*reinterpret_cast<const __half2*>(&u[i]));
            xr2[i] = pk2(t.x, t.y);
        }
        u = &hb.x;
#pragma unroll
        for (int i = 0; i < 4; i++) {
            float2 t = __half22float2(*reinterpret_cast<const __half2*>(&u[i]));
            xr2[4 + i] = pk2(t.x, t.y);
        }
    }
    u64 at2[8];
    {
        const float4* ap = reinterpret_cast<const float4*>(att + (size_t)layer * HD + lane * 16);
#pragma unroll
        for (int i = 0; i < 4; i++) {
            float4 v = ap[i];
            at2[2 * i]     = pk2(v.x, v.y);
            at2[2 * i + 1] = pk2(v.z, v.w);
        }
    }

    u64 acc2[8];
#pragma unroll
    for (int i = 0; i < 8; i++) acc2[i] = 0ull;
    float den = 0.f;

    int beg = g_rowptr[node], end = g_rowptr[node + 1];

    ulonglong2 r0, r1, r2, r3;   // prefetched xl row (64B/lane = 16 floats)
    {
        int s0 = __ldg(&g_srcs[beg]);
        const ulonglong2* q = reinterpret_cast<const ulonglong2*>(g_xl + (size_t)s0 * HD + lane * 16);
        r0 = q[0]; r1 = q[1]; r2 = q[2]; r3 = q[3];
    }
    for (int e = beg; e < end; e++) {
        u64 v2[8];
        v2[0] = r0.x; v2[1] = r0.y; v2[2] = r1.x; v2[3] = r1.y;
        v2[4] = r2.x; v2[5] = r2.y; v2[6] = r3.x; v2[7] = r3.y;
        if (e + 1 < end) {
            int sn = __ldg(&g_srcs[e + 1]);
            const ulonglong2* q = reinterpret_cast<const ulonglong2*>(g_xl + (size_t)sn * HD + lane * 16);
            r0 = q[0]; r1 = q[1]; r2 = q[2]; r3 = q[3];
        }
        // logit: sum lrelu(v+xr)*att over 16 channels, packed
        u64 p2 = 0ull;
#pragma unroll
        for (int q = 0; q < 8; q++) {
            u64 t = add2(v2[q], xr2[q]);
            u64 a = t & ABS2;
            u64 m = mul2(a, C04);
            fma2(m, t, C06);          // m = 0.6t + 0.4|t| = lrelu(t)
            fma2(p2, m, at2[q]);
        }
        float plo, phi;
        upk2(p2, plo, phi);
        float p = plo + phi;
        p += __shfl_xor_sync(0xffffffffu, p, 2);
        p += __shfl_xor_sync(0xffffffffu, p, 1);   // head logit
        float w = __expf(p);
        den += w;
        u64 w2 = pk2(w, w);
#pragma unroll
        for (int q = 0; q < 8; q++) fma2(acc2[q], v2[q], w2);
    }

    // unpack, normalize by head denom, head-mean via shuffles
    float acc[16];
#pragma unroll
    for (int q = 0; q < 8; q++) upk2(acc2[q], acc[2 * q], acc[2 * q + 1]);

    float inv = 1.f / den;
#pragma unroll
    for (int i = 0; i < 16; i++) {
        float a = acc[i] * inv;
        a += __shfl_xor_sync(0xffffffffu, a, 16);
        a += __shfl_xor_sync(0xffffffffu, a, 8);
        a += __shfl_xor_sync(0xffffffffu, a, 4);
        acc[i] = a;                        // head-sum, valid per q=lane&3
    }

    if (lane < 4) {                        // lanes 0..3 own channels q*16..q*16+15
        float v[16];
        const float4* bp = reinterpret_cast<const float4*>(bb + (size_t)layer * DD + lane * 16);
        const float4* xp = reinterpret_cast<const float4*>(xprev + (size_t)node * DD + lane * 16);
        float s1 = 0.f, s2 = 0.f;
#pragma unroll
        for (int i = 0; i < 4; i++) {
            float4 bv = bp[i], xv = xp[i];
            v[4 * i + 0] = acc[4 * i + 0] * 0.125f + bv.x + xv.x;
            v[4 * i + 1] = acc[4 * i + 1] * 0.125f + bv.y + xv.y;
            v[4 * i + 2] = acc[4 * i + 2] * 0.125f + bv.z + xv.z;
            v[4 * i + 3] = acc[4 * i + 3] * 0.125f + bv.w + xv.w;
        }
#pragma unroll
        for (int i = 0; i < 16; i++) { s1 += v[i]; s2 += v[i] * v[i]; }
        s1 += __shfl_xor_sync(0xFu, s1, 2);
        s1 += __shfl_xor_sync(0xFu, s1, 1);
        s2 += __shfl_xor_sync(0xFu, s2, 2);
        s2 += __shfl_xor_sync(0xFu, s2, 1);
        float mean = s1 * (1.f / DD);
        float var  = s2 * (1.f / DD) - mean * mean;
        float rstd = rsqrtf(var + LN_EPS);
        const float4* gp = reinterpret_cast<const float4*>(gam + (size_t)layer * DD + lane * 16);
        const float4* ep = reinterpret_cast<const float4*>(bet + (size_t)layer * DD + lane * 16);
        float4* op = reinterpret_cast<float4*>(xnext + (size_t)node * DD + lane * 16);
#pragma unroll
        for (int i = 0; i < 4; i++) {
            float4 gv = gp[i], bv = ep[i], o;
            o.x = fmaxf((v[4 * i + 0] - mean) * rstd * gv.x + bv.x, 0.f);
            o.y = fmaxf((v[4 * i + 1] - mean) * rstd * gv.y + bv.y, 0.f);
            o.z = fmaxf((v[4 * i + 2] - mean) * rstd * gv.z + bv.z, 0.f);
            o.w = fmaxf((v[4 * i + 3] - mean) * rstd * gv.w + bv.w, 0.f);
            op[i] = o;
        }
    }
}

// ---------------- launch ---------------------------------------------------
extern "C" void kernel_launch(void* const* d_in, const int* in_sizes, int n_in,
                              void* d_out, int out_size) {
    const float* x   = (const float*)d_in[0];
    const float* Wl  = (const float*)d_in[1];
    const float* Wr  = (const float*)d_in[2];
    const float* att = (const float*)d_in[3];
    const float* b   = (const float*)d_in[4];
    const float* gam = (const float*)d_in[5];
    const float* bet = (const float*)d_in[6];
    const void*  ei  = (const void*)d_in[7];
    float* out = (float*)d_out;

    dim3 ggrid(NN / GNT, 2);

    zero_detect_kernel<<<(NN + 255) / 256, 256>>>(ei);   // 1
    count_kernel<<<(ET + 255) / 256, 256>>>(ei);         // 2
    scan1_kernel<<<NSB, 512>>>();                        // 3
    gemm_kernel<<<ggrid, 256>>>(x, Wl, Wr, 0);           // 4 <- profiler slot
    scan2_kernel<<<1, 128>>>();                          // 5
    scan3_kernel<<<NSB, 512>>>();                        // 6
    scatter_kernel<<<(ET + 255) / 256, 256>>>(ei);       // 7

    const float* xin[3]  = { x, g_xb, g_xa };
    float*       xout[3] = { g_xb, g_xa, out };

    for (int l = 0; l < 3; l++) {
        if (l > 0) gemm_kernel<<<ggrid, 256>>>(xin[l], Wl, Wr, l);
        edge_node_kernel<<<NN / 8, 256>>>(att, b, gam, bet, xin[l], xout[l], l);
    }
}

// round 14
// speedup vs baseline: 1.1374x; 1.1374x over previous
#include <cuda_runtime.h>
#include <cuda_fp16.h>

// Problem constants
#define NN 50000
#define DD 64
#define HH 8
#define HD 512          // H * D
#define EE 400000
#define ET (EE + NN)    // edges + self loops
#define LN_EPS 1e-5f
#define NEG 0.2f
#define GNT 16          // nodes per GEMM block tile
#define XSP 20          // padded smem row stride (floats); 16B-aligned rows
#define NSB 98          // scan blocks

typedef unsigned long long u64;

// ---------------- scratch (static device memory) ---------------------------
__device__ __align__(16) __half g_xl[(size_t)NN * HD];  // 51.2 MB (L2-resident)
__device__ __align__(16) __half g_xr[(size_t)NN * HD];  // 51.2 MB
__device__ __align__(16) float  g_xa[NN * DD];
__device__ __align__(16) float  g_xb[NN * DD];
__device__ int g_rowptr[NN + 1];
__device__ int g_cnt[NN];
__device__ int g_srcs[ET];
__device__ int g_is64;
__device__ int g_bsum[NSB];
__device__ int g_boff[NSB];

// ---------------- packed f32x2 helpers --------------------------------------
__device__ __forceinline__ u64 pk2(float lo, float hi) {
    u64 r;
    asm("mov.b64 %0, {%1, %2};" : "=l"(r) : "f"(lo), "f"(hi));
    return r;
}
__device__ __forceinline__ void upk2(u64 v, float& lo, float& hi) {
    asm("mov.b64 {%0, %1}, %2;" : "=f"(lo), "=f"(hi) : "l"(v));
}
__device__ __forceinline__ void fma2(u64& d, u64 a, u64 b) {   // d += a*b
    asm("fma.rn.f32x2 %0, %1, %2, %0;" : "+l"(d) : "l"(a), "l"(b));
}
__device__ __forceinline__ u64 add2(u64 a, u64 b) {
    u64 r;
    asm("add.rn.f32x2 %0, %1, %2;" : "=l"(r) : "l"(a), "l"(b));
    return r;
}
__device__ __forceinline__ u64 mul2(u64 a, u64 b) {
    u64 r;
    asm("mul.rn.f32x2 %0, %1, %2;" : "=l"(r) : "l"(a), "l"(b));
    return r;
}
__device__ __forceinline__ u64 h2tof2(unsigned h) {   // half2 -> packed f32x2
    float2 t = __half22float2(*reinterpret_cast<const __half2*>(&h));
    return pk2(t.x, t.y);
}
__device__ __forceinline__ int edge_at(const void* ei, int i, int is64) {
    if (is64) return (int)((const long long*)ei)[i];
    return ((const int*)ei)[i];
}

// ---------------- CSR build ------------------------------------------------
__global__ void zero_detect_kernel(const void* ei) {
    int i = blockIdx.x * blockDim.x + threadIdx.x;
    if (i < NN) g_cnt[i] = 0;
    if (i == 0) {
        const u64* p = (const u64*)ei;
        int is64 = 1;
        for (int k = 0; k < 16; k++)
            if (p[k] >= (u64)NN) { is64 = 0; break; }
        g_is64 = is64;
    }
}

__global__ void count_kernel(const void* __restrict__ ei) {
    int e = blockIdx.x * blockDim.x + threadIdx.x;
    if (e >= ET) return;
    int is64 = g_is64;
    int dst = (e < EE) ? edge_at(ei, EE + e, is64) : (e - EE);
    atomicAdd(&g_cnt[dst], 1);
}

__global__ void scan1_kernel() {
    __shared__ int ws[16];
    int tid = threadIdx.x, lane = tid & 31, w = tid >> 5;
    int i = blockIdx.x * 512 + tid;
    int v = (i < NN) ? g_cnt[i] : 0;
    int x = v;
#pragma unroll
    for (int off = 1; off < 32; off <<= 1) {
        int t = __shfl_up_sync(0xffffffffu, x, off);
        if (lane >= off) x += t;
    }
    if (lane == 31) ws[w] = x;
    __syncthreads();
    if (w == 0) {
        int y = (lane < 16) ? ws[lane] : 0;
#pragma unroll
        for (int off = 1; off < 16; off <<= 1) {
            int t = __shfl_up_sync(0xffffffffu, y, off);
            if (lane >= off) y += t;
        }
        if (lane < 16) ws[lane] = y;
    }
    __syncthreads();
    int incl = x + (w ? ws[w - 1] : 0);
    if (i < NN) g_rowptr[i + 1] = incl;
    if (tid == 511) g_bsum[blockIdx.x] = incl;
}

__global__ void scan2_kernel() {
    __shared__ int ws[4];
    int t = threadIdx.x, lane = t & 31, w = t >> 5;
    int v = (t < NSB) ? g_bsum[t] : 0;
    int x = v;
#pragma unroll
    for (int off = 1; off < 32; off <<= 1) {
        int u = __shfl_up_sync(0xffffffffu, x, off);
        if (lane >= off) x += u;
    }
    if (lane == 31) ws[w] = x;
    __syncthreads();
    if (t == 0) {
        int r = 0;
#pragma unroll
        for (int q = 0; q < 4; q++) { int s = ws[q]; ws[q] = r; r += s; }
        g_rowptr[0] = 0;
    }
    __syncthreads();
    if (t < NSB) g_boff[t] = x - v + ws[w];
}

__global__ void scan3_kernel() {   // add offsets + re-zero cnt
    int i = blockIdx.x * 512 + threadIdx.x;
    if (i < NN) {
        g_rowptr[i + 1] += g_boff[blockIdx.x];
        g_cnt[i] = 0;
    }
}

__global__ void scatter_kernel(const void* __restrict__ ei) {
    int e = blockIdx.x * blockDim.x + threadIdx.x;
    if (e >= ET) return;
    int is64 = g_is64;
    int src, dst;
    if (e < EE) { src = edge_at(ei, e, is64); dst = edge_at(ei, EE + e, is64); }
    else        { src = dst = e - EE; }
    int pos = g_rowptr[dst] + atomicAdd(&g_cnt[dst], 1);
    g_srcs[pos] = src;
}

// ---------------- GEMM: g_xl/g_xr (fp16) = xin @ Wl/Wr ---------------------
// 256 threads, 16 nodes/block. LDS.128 xs loads (4/k) + fp16 stores.
__global__ void __launch_bounds__(256)
gemm_kernel(const float* __restrict__ xin,
            const float* __restrict__ Wl, const float* __restrict__ Wr,
            int layer) {
    __shared__ __align__(16) float xs[DD][XSP];
    int tid = threadIdx.x;
    int n0  = blockIdx.x * GNT;
    int side = blockIdx.y;
    const float* W = (side ? Wr : Wl) + (size_t)layer * DD * HD;
    __half* out = side ? g_xr : g_xl;

    for (int i = tid; i < GNT * DD; i += 256) {
        int n = i >> 6, k = i & 63;
        xs[k][n] = xin[(n0 + n) * DD + k];
    }
    __syncthreads();

    int j0 = tid, j1 = tid + 256;
    u64 acc0[GNT / 2], acc1[GNT / 2];
#pragma unroll
    for (int p = 0; p < GNT / 2; p++) { acc0[p] = 0ull; acc1[p] = 0ull; }

#pragma unroll 4
    for (int k = 0; k < DD; k++) {
        float w0 = __ldg(&W[k * HD + j0]);
        float w1 = __ldg(&W[k * HD + j1]);
        u64 w02 = pk2(w0, w0);
        u64 w12 = pk2(w1, w1);
        ulonglong2 q0 = *reinterpret_cast<const ulonglong2*>(&xs[k][0]);
        ulonglong2 q1 = *reinterpret_cast<const ulonglong2*>(&xs[k][4]);
        ulonglong2 q2 = *reinterpret_cast<const ulonglong2*>(&xs[k][8]);
        ulonglong2 q3 = *reinterpret_cast<const ulonglong2*>(&xs[k][12]);
        fma2(acc0[0], q0.x, w02); fma2(acc1[0], q0.x, w12);
        fma2(acc0[1], q0.y, w02); fma2(acc1[1], q0.y, w12);
        fma2(acc0[2], q1.x, w02); fma2(acc1[2], q1.x, w12);
        fma2(acc0[3], q1.y, w02); fma2(acc1[3], q1.y, w12);
        fma2(acc0[4], q2.x, w02); fma2(acc1[4], q2.x, w12);
        fma2(acc0[5], q2.y, w02); fma2(acc1[5], q2.y, w12);
        fma2(acc0[6], q3.x, w02); fma2(acc1[6], q3.x, w12);
        fma2(acc0[7], q3.y, w02); fma2(acc1[7], q3.y, w12);
    }

#pragma unroll
    for (int p = 0; p < GNT / 2; p++) {
        float a, b;
        upk2(acc0[p], a, b);
        out[(size_t)(n0 + 2 * p) * HD + j0]     = __float2half_rn(a);
        out[(size_t)(n0 + 2 * p + 1) * HD + j0] = __float2half_rn(b);
        upk2(acc1[p], a, b);
        out[(size_t)(n0 + 2 * p) * HD + j1]     = __float2half_rn(a);
        out[(size_t)(n0 + 2 * p + 1) * HD + j1] = __float2half_rn(b);
    }
}

// ---------------- fused edge attention + aggregation + node epilogue -------
// WARP-per-node; lane owns 16 channels. xl gathered fp16 (32B/lane),
// converted to 8 packed f32x2 pairs; logit + accumulate in f32x2.
// Branch-free lrelu 0.6t+0.4|t|. No-max softmax (logits bounded << 88).
__global__ void __launch_bounds__(256)
edge_node_kernel(const float* __restrict__ att, const float* __restrict__ bb,
                 const float* __restrict__ gam, const float* __restrict__ bet,
                 const float* __restrict__ xprev, float* __restrict__ xnext,
                 int layer) {
    int lane = threadIdx.x & 31;
    int node = blockIdx.x * 8 + (threadIdx.x >> 5);   // 50000 = 6250*8

    const u64 ABS2 = 0x7FFFFFFF7FFFFFFFull;
    const u64 C06  = pk2(0.6f, 0.6f);
    const u64 C04  = pk2(0.4f, 0.4f);

    // xr (fp16) -> packed f32x2 pairs
    u64 xr2[8];
    {
        const uint4* xp = reinterpret_cast<const uint4*>(g_xr + (size_t)node * HD + lane * 16);
        uint4 ha = xp[0], hb = xp[1];
        const unsigned* u = &ha.x;
#pragma unroll
        for (int i = 0; i < 4; i++) xr2[i] = h2tof2(u[i]);
        u = &hb.x;
#pragma unroll
        for (int i = 0; i < 4; i++) xr2[4 + i] = h2tof2(u[i]);
    }
    u64 at2[8];
    {
        const float4* ap = reinterpret_cast<const float4*>(att + (size_t)layer * HD + lane * 16);
#pragma unroll
        for (int i = 0; i < 4; i++) {
            float4 v = ap[i];
            at2[2 * i]     = pk2(v.x, v.y);
            at2[2 * i + 1] = pk2(v.z, v.w);
        }
    }

    u64 acc2[8];
#pragma unroll
    for (int i = 0; i < 8; i++) acc2[i] = 0ull;
    float den = 0.f;

    int beg = g_rowptr[node], end = g_rowptr[node + 1];

    uint4 ra, rb;                    // prefetched fp16 xl row (32B/lane)
    {
        int s0 = __ldg(&g_srcs[beg]);
        const uint4* q = reinterpret_cast<const uint4*>(g_xl + (size_t)s0 * HD + lane * 16);
        ra = q[0]; rb = q[1];
    }
    for (int e = beg; e < end; e++) {
        u64 v2[8];
        {
            const unsigned* u = &ra.x;
#pragma unroll
            for (int i = 0; i < 4; i++) v2[i] = h2tof2(u[i]);
            u = &rb.x;
#pragma unroll
            for (int i = 0; i < 4; i++) v2[4 + i] = h2tof2(u[i]);
        }
        if (e + 1 < end) {
            int sn = __ldg(&g_srcs[e + 1]);
            const uint4* q = reinterpret_cast<const uint4*>(g_xl + (size_t)sn * HD + lane * 16);
            ra = q[0]; rb = q[1];
        }
        // logit: sum lrelu(v+xr)*att over 16 channels, packed
        u64 p2 = 0ull;
#pragma unroll
        for (int q = 0; q < 8; q++) {
            u64 t = add2(v2[q], xr2[q]);
            u64 a = t & ABS2;
            u64 m = mul2(a, C04);
            fma2(m, t, C06);          // m = 0.6t + 0.4|t| = lrelu(t)
            fma2(p2, m, at2[q]);
        }
        float plo, phi;
        upk2(p2, plo, phi);
        float p = plo + phi;
        p += __shfl_xor_sync(0xffffffffu, p, 2);
        p += __shfl_xor_sync(0xffffffffu, p, 1);   // head logit
        float w = __expf(p);
        den += w;
        u64 w2 = pk2(w, w);
#pragma unroll
        for (int q = 0; q < 8; q++) fma2(acc2[q], v2[q], w2);
    }

    // unpack, normalize by head denom, head-mean via shuffles
    float acc[16];
#pragma unroll
    for (int q = 0; q < 8; q++) upk2(acc2[q], acc[2 * q], acc[2 * q + 1]);

    float inv = 1.f / den;
#pragma unroll
    for (int i = 0; i < 16; i++) {
        float a = acc[i] * inv;
        a += __shfl_xor_sync(0xffffffffu, a, 16);
        a += __shfl_xor_sync(0xffffffffu, a, 8);
        a += __shfl_xor_sync(0xffffffffu, a, 4);
        acc[i] = a;                        // head-sum, valid per q=lane&3
    }

    if (lane < 4) {                        // lanes 0..3 own channels q*16..q*16+15
        float v[16];
        const float4* bp = reinterpret_cast<const float4*>(bb + (size_t)layer * DD + lane * 16);
        const float4* xp = reinterpret_cast<const float4*>(xprev + (size_t)node * DD + lane * 16);
        float s1 = 0.f, s2 = 0.f;
#pragma unroll
        for (int i = 0; i < 4; i++) {
            float4 bv = bp[i], xv = xp[i];
            v[4 * i + 0] = acc[4 * i + 0] * 0.125f + bv.x + xv.x;
            v[4 * i + 1] = acc[4 * i + 1] * 0.125f + bv.y + xv.y;
            v[4 * i + 2] = acc[4 * i + 2] * 0.125f + bv.z + xv.z;
            v[4 * i + 3] = acc[4 * i + 3] * 0.125f + bv.w + xv.w;
        }
#pragma unroll
        for (int i = 0; i < 16; i++) { s1 += v[i]; s2 += v[i] * v[i]; }
        s1 += __shfl_xor_sync(0xFu, s1, 2);
        s1 += __shfl_xor_sync(0xFu, s1, 1);
        s2 += __shfl_xor_sync(0xFu, s2, 2);
        s2 += __shfl_xor_sync(0xFu, s2, 1);
        float mean = s1 * (1.f / DD);
        float var  = s2 * (1.f / DD) - mean * mean;
        float rstd = rsqrtf(var + LN_EPS);
        const float4* gp = reinterpret_cast<const float4*>(gam + (size_t)layer * DD + lane * 16);
        const float4* ep = reinterpret_cast<const float4*>(bet + (size_t)layer * DD + lane * 16);
        float4* op = reinterpret_cast<float4*>(xnext + (size_t)node * DD + lane * 16);
#pragma unroll
        for (int i = 0; i < 4; i++) {
            float4 gv = gp[i], bv = ep[i], o;
            o.x = fmaxf((v[4 * i + 0] - mean) * rstd * gv.x + bv.x, 0.f);
            o.y = fmaxf((v[4 * i + 1] - mean) * rstd * gv.y + bv.y, 0.f);
            o.z = fmaxf((v[4 * i + 2] - mean) * rstd * gv.z + bv.z, 0.f);
            o.w = fmaxf((v[4 * i + 3] - mean) * rstd * gv.w + bv.w, 0.f);
            op[i] = o;
        }
    }
}

// ---------------- launch ---------------------------------------------------
extern "C" void kernel_launch(void* const* d_in, const int* in_sizes, int n_in,
                              void* d_out, int out_size) {
    const float* x   = (const float*)d_in[0];
    const float* Wl  = (const float*)d_in[1];
    const float* Wr  = (const float*)d_in[2];
    const float* att = (const float*)d_in[3];
    const float* b   = (const float*)d_in[4];
    const float* gam = (const float*)d_in[5];
    const float* bet = (const float*)d_in[6];
    const void*  ei  = (const void*)d_in[7];
    float* out = (float*)d_out;

    dim3 ggrid(NN / GNT, 2);

    zero_detect_kernel<<<(NN + 255) / 256, 256>>>(ei);   // 1
    count_kernel<<<(ET + 255) / 256, 256>>>(ei);         // 2
    scan1_kernel<<<NSB, 512>>>();                        // 3
    gemm_kernel<<<ggrid, 256>>>(x, Wl, Wr, 0);           // 4 <- profiler slot
    scan2_kernel<<<1, 128>>>();                          // 5
    scan3_kernel<<<NSB, 512>>>();                        // 6
    scatter_kernel<<<(ET + 255) / 256, 256>>>(ei);       // 7

    const float* xin[3]  = { x, g_xb, g_xa };
    float*       xout[3] = { g_xb, g_xa, out };

    for (int l = 0; l < 3; l++) {
        if (l > 0) gemm_kernel<<<ggrid, 256>>>(xin[l], Wl, Wr, l);
        edge_node_kernel<<<NN / 8, 256>>>(att, b, gam, bet, xin[l], xout[l], l);
    }
}

// round 15
// speedup vs baseline: 1.2200x; 1.0726x over previous
#include <cuda_runtime.h>
#include <cuda_fp16.h>
#include <mma.h>
using namespace nvcuda;

// Problem constants
#define NN 50000
#define DD 64
#define HH 8
#define HD 512          // H * D
#define EE 400000
#define ET (EE + NN)    // edges + self loops
#define LN_EPS 1e-5f
#define NSB 98          // scan blocks

// wmma GEMM tiling
#define MCH 64          // nodes per chunk
#define NBC 128         // cols per block
#define NCHUNK 782      // ceil(50048/64) covers NN
#define PPART 37        // M partitions -> 4*2*37 = 296 blocks = 2/SM

// mm_kernel dynamic smem layout (bytes)
#define SX_H 0
#define SX_L 10240
#define SW_H 20480
#define SW_L 38912
#define SC_F 57344
#define SM_BYTES 90112

typedef unsigned long long u64;

// ---------------- scratch (static device memory) ---------------------------
__device__ __align__(16) __half g_xl[(size_t)NN * HD];  // 51.2 MB
__device__ __align__(16) __half g_xr[(size_t)NN * HD];  // 51.2 MB
__device__ __align__(16) float  g_xa[NN * DD];
__device__ __align__(16) float  g_xb[NN * DD];
__device__ __align__(16) __half g_xh[NN * DD];          // x hi (fp16)
__device__ __align__(16) __half g_xlo[NN * DD];         // x lo (fp16 residual)
__device__ __align__(16) __half g_wh[2 * DD * HD];      // W hi, [side][k][j]
__device__ __align__(16) __half g_wl[2 * DD * HD];      // W lo
__device__ int g_rowptr[NN + 1];
__device__ int g_cnt[NN];
__device__ int g_srcs[ET];
__device__ int g_is64;
__device__ int g_bsum[NSB];
__device__ int g_boff[NSB];

// ---------------- helpers --------------------------------------------------
__device__ __forceinline__ float lrelu(float x) { return x > 0.f ? x : 0.2f * x; }
__device__ __forceinline__ int edge_at(const void* ei, int i, int is64) {
    if (is64) return (int)((const long long*)ei)[i];
    return ((const int*)ei)[i];
}
// convert 16 packed halves (2x uint4) -> float[16]
__device__ __forceinline__ void cvt16(float* f, uint4 a, uint4 b) {
    const unsigned* u = &a.x;
#pragma unroll
    for (int i = 0; i < 4; i++) {
        float2 t = __half22float2(*reinterpret_cast<const __half2*>(&u[i]));
        f[2 * i] = t.x; f[2 * i + 1] = t.y;
    }
    u = &b.x;
#pragma unroll
    for (int i = 0; i < 4; i++) {
        float2 t = __half22float2(*reinterpret_cast<const __half2*>(&u[i]));
        f[8 + 2 * i] = t.x; f[9 + 2 * i] = t.y;
    }
}

// ---------------- hi/lo fp16 prep ------------------------------------------
__global__ void xprep_kernel(const float* __restrict__ xin) {
    int i = blockIdx.x * 256 + threadIdx.x;
    if (i < NN * DD) {
        float v = xin[i];
        __half h = __float2half_rn(v);
        g_xh[i]  = h;
        g_xlo[i] = __float2half_rn(v - __half2float(h));
    }
}

__global__ void wprep_kernel(const float* __restrict__ Wl,
                             const float* __restrict__ Wr, int layer) {
    int i = blockIdx.x * 256 + threadIdx.x;
    int side = blockIdx.y;
    if (i < DD * HD) {
        const float* W = (side ? Wr : Wl) + (size_t)layer * DD * HD;
        float v = W[i];
        __half h = __float2half_rn(v);
        g_wh[side * (DD * HD) + i] = h;
        g_wl[side * (DD * HD) + i] = __float2half_rn(v - __half2float(h));
    }
}

// ---------------- CSR build ------------------------------------------------
__global__ void zero_detect_kernel(const void* ei) {
    int i = blockIdx.x * blockDim.x + threadIdx.x;
    if (i < NN) g_cnt[i] = 0;
    if (i == 0) {
        const u64* p = (const u64*)ei;
        int is64 = 1;
        for (int k = 0; k < 16; k++)
            if (p[k] >= (u64)NN) { is64 = 0; break; }
        g_is64 = is64;
    }
}

__global__ void count_kernel(const void* __restrict__ ei) {
    int e = blockIdx.x * blockDim.x + threadIdx.x;
    if (e >= ET) return;
    int is64 = g_is64;
    int dst = (e < EE) ? edge_at(ei, EE + e, is64) : (e - EE);
    atomicAdd(&g_cnt[dst], 1);
}

__global__ void scan1_kernel() {
    __shared__ int ws[16];
    int tid = threadIdx.x, lane = tid & 31, w = tid >> 5;
    int i = blockIdx.x * 512 + tid;
    int v = (i < NN) ? g_cnt[i] : 0;
    int x = v;
#pragma unroll
    for (int off = 1; off < 32; off <<= 1) {
        int t = __shfl_up_sync(0xffffffffu, x, off);
        if (lane >= off) x += t;
    }
    if (lane == 31) ws[w] = x;
    __syncthreads();
    if (w == 0) {
        int y = (lane < 16) ? ws[lane] : 0;
#pragma unroll
        for (int off = 1; off < 16; off <<= 1) {
            int t = __shfl_up_sync(0xffffffffu, y, off);
            if (lane >= off) y += t;
        }
        if (lane < 16) ws[lane] = y;
    }
    __syncthreads();
    int incl = x + (w ? ws[w - 1] : 0);
    if (i < NN) g_rowptr[i + 1] = incl;
    if (tid == 511) g_bsum[blockIdx.x] = incl;
}

__global__ void scan2_kernel() {
    __shared__ int ws[4];
    int t = threadIdx.x, lane = t & 31, w = t >> 5;
    int v = (t < NSB) ? g_bsum[t] : 0;
    int x = v;
#pragma unroll
    for (int off = 1; off < 32; off <<= 1) {
        int u = __shfl_up_sync(0xffffffffu, x, off);
        if (lane >= off) x += u;
    }
    if (lane == 31) ws[w] = x;
    __syncthreads();
    if (t == 0) {
        int r = 0;
#pragma unroll
        for (int q = 0; q < 4; q++) { int s = ws[q]; ws[q] = r; r += s; }
        g_rowptr[0] = 0;
    }
    __syncthreads();
    if (t < NSB) g_boff[t] = x - v + ws[w];
}

__global__ void scan3_kernel() {   // add offsets + re-zero cnt
    int i = blockIdx.x * 512 + threadIdx.x;
    if (i < NN) {
        g_rowptr[i + 1] += g_boff[blockIdx.x];
        g_cnt[i] = 0;
    }
}

__global__ void scatter_kernel(const void* __restrict__ ei) {
    int e = blockIdx.x * blockDim.x + threadIdx.x;
    if (e >= ET) return;
    int is64 = g_is64;
    int src, dst;
    if (e < EE) { src = edge_at(ei, e, is64); dst = edge_at(ei, EE + e, is64); }
    else        { src = dst = e - EE; }
    int pos = g_rowptr[dst] + atomicAdd(&g_cnt[dst], 1);
    g_srcs[pos] = src;
}

// ---------------- wmma GEMM: g_xl/g_xr (fp16) = x @ W ----------------------
// Compensated fp16: D = Ah*Bh + Ah*Bl + Al*Bh (~fp32 accuracy).
// grid (4 col-groups, 2 sides, 37 partitions); 256 threads = 8 warps
// (2 m-groups x 4 n-groups; each warp 2x2 m16n16k16 tiles).
// W slice [64][128] hi/lo held in smem across the block's whole M loop.
__global__ void __launch_bounds__(256, 2)
mm_kernel() {
    extern __shared__ __align__(32) char smraw[];
    __half* sxh = (__half*)(smraw + SX_H);   // [64][80]
    __half* sxl = (__half*)(smraw + SX_L);   // [64][80]
    __half* swh = (__half*)(smraw + SW_H);   // [64][144]
    __half* swl = (__half*)(smraw + SW_L);   // [64][144]
    float*  sC  = (float*)(smraw + SC_F);    // [64][128]

    int tid  = threadIdx.x;
    int warp = tid >> 5;
    int mg = warp >> 2;            // 0..1 : rows mg*32
    int ng = warp & 3;             // 0..3 : cols ng*32
    int cg   = blockIdx.x;
    int side = blockIdx.y;
    int p    = blockIdx.z;
    int col0 = cg * NBC;
    __half* outp = side ? g_xr : g_xl;
    const __half* wh = g_wh + side * (DD * HD);
    const __half* wl = g_wl + side * (DD * HD);

    // load W slice [64][128] hi/lo once
    for (int i = tid; i < 64 * 16; i += 256) {
        int r = i >> 4, c = i & 15;
        *(uint4*)(swh + r * 144 + c * 8) = *(const uint4*)(wh + r * HD + col0 + c * 8);
        *(uint4*)(swl + r * 144 + c * 8) = *(const uint4*)(wl + r * HD + col0 + c * 8);
    }

    for (int ch = p; ch < NCHUNK; ch += PPART) {
        int node0 = ch * MCH;
        // load x chunk [64][64] hi/lo (zero-pad past NN)
        for (int i = tid; i < 64 * 8; i += 256) {
            int r = i >> 3, c = i & 7;
            uint4 vh = make_uint4(0, 0, 0, 0), vlo = vh;
            if (node0 + r < NN) {
                vh  = *(const uint4*)(g_xh  + (size_t)(node0 + r) * DD + c * 8);
                vlo = *(const uint4*)(g_xlo + (size_t)(node0 + r) * DD + c * 8);
            }
            *(uint4*)(sxh + r * 80 + c * 8) = vh;
            *(uint4*)(sxl + r * 80 + c * 8) = vlo;
        }
        __syncthreads();

        wmma::fragment<wmma::accumulator, 16, 16, 16, float> cf[2][2];
#pragma unroll
        for (int a = 0; a < 2; a++)
#pragma unroll
            for (int b = 0; b < 2; b++) wmma::fill_fragment(cf[a][b], 0.f);

#pragma unroll
        for (int k = 0; k < 4; k++) {
            wmma::fragment<wmma::matrix_a, 16, 16, 16, __half, wmma::row_major> ah[2], al[2];
            wmma::fragment<wmma::matrix_b, 16, 16, 16, __half, wmma::row_major> bh[2], bl[2];
#pragma unroll
            for (int mi = 0; mi < 2; mi++) {
                wmma::load_matrix_sync(ah[mi], sxh + (mg * 32 + mi * 16) * 80 + k * 16, 80);
                wmma::load_matrix_sync(al[mi], sxl + (mg * 32 + mi * 16) * 80 + k * 16, 80);
            }
#pragma unroll
            for (int ni = 0; ni < 2; ni++) {
                wmma::load_matrix_sync(bh[ni], swh + (k * 16) * 144 + ng * 32 + ni * 16, 144);
                wmma::load_matrix_sync(bl[ni], swl + (k * 16) * 144 + ng * 32 + ni * 16, 144);
            }
#pragma unroll
            for (int mi = 0; mi < 2; mi++)
#pragma unroll
                for (int ni = 0; ni < 2; ni++) {
                    wmma::mma_sync(cf[mi][ni], ah[mi], bh[ni], cf[mi][ni]);
                    wmma::mma_sync(cf[mi][ni], ah[mi], bl[ni], cf[mi][ni]);
                    wmma::mma_sync(cf[mi][ni], al[mi], bh[ni], cf[mi][ni]);
                }
        }
        __syncthreads();   // all mma reads done before sC writes / x reuse
#pragma unroll
        for (int mi = 0; mi < 2; mi++)
#pragma unroll
            for (int ni = 0; ni < 2; ni++)
                wmma::store_matrix_sync(sC + (mg * 32 + mi * 16) * 128 + ng * 32 + ni * 16,
                                        cf[mi][ni], 128, wmma::mem_row_major);
        __syncthreads();
        // convert fp32 smem -> fp16 global
        for (int i = tid; i < 64 * 32; i += 256) {
            int r = i >> 5, c4 = i & 31;
            if (node0 + r < NN) {
                float4 v = *(float4*)(sC + r * 128 + c4 * 4);
                __half2 h0 = __floats2half2_rn(v.x, v.y);
                __half2 h1 = __floats2half2_rn(v.z, v.w);
                uint2 pk;
                pk.x = *reinterpret_cast<unsigned*>(&h0);
                pk.y = *reinterpret_cast<unsigned*>(&h1);
                *(uint2*)(outp + (size_t)(node0 + r) * HD + col0 + c4 * 4) = pk;
            }
        }
        __syncthreads();
    }
}

// ---------------- fused edge attention + aggregation + node epilogue -------
// (R11 version verbatim: warp-per-node, scalar cvt16, no-max softmax)
__global__ void __launch_bounds__(256)
edge_node_kernel(const float* __restrict__ att, const float* __restrict__ bb,
                 const float* __restrict__ gam, const float* __restrict__ bet,
                 const float* __restrict__ xprev, float* __restrict__ xnext,
                 int layer) {
    int lane = threadIdx.x & 31;
    int node = blockIdx.x * 8 + (threadIdx.x >> 5);   // 50000 = 6250*8 exact

    const uint4* xrp = reinterpret_cast<const uint4*>(g_xr + (size_t)node * HD + lane * 16);
    float xr[16];
    cvt16(xr, xrp[0], xrp[1]);
    float at[16];
    {
        const float4* ap = reinterpret_cast<const float4*>(att + (size_t)layer * HD + lane * 16);
#pragma unroll
        for (int i = 0; i < 4; i++) {
            float4 v = ap[i];
            at[4 * i] = v.x; at[4 * i + 1] = v.y; at[4 * i + 2] = v.z; at[4 * i + 3] = v.w;
        }
    }

    float acc[16];
#pragma unroll
    for (int i = 0; i < 16; i++) acc[i] = 0.f;
    float den = 0.f;

    int beg = g_rowptr[node], end = g_rowptr[node + 1];

    uint4 ra, rb;
    {
        int s0 = __ldg(&g_srcs[beg]);
        const uint4* q = reinterpret_cast<const uint4*>(g_xl + (size_t)s0 * HD + lane * 16);
        ra = q[0]; rb = q[1];
    }
    for (int e = beg; e < end; e++) {
        float v[16];
        cvt16(v, ra, rb);
        if (e + 1 < end) {
            int sn = __ldg(&g_srcs[e + 1]);
            const uint4* q = reinterpret_cast<const uint4*>(g_xl + (size_t)sn * HD + lane * 16);
            ra = q[0]; rb = q[1];
        }
        float pl = 0.f;
#pragma unroll
        for (int i = 0; i < 16; i++) pl += lrelu(v[i] + xr[i]) * at[i];
        pl += __shfl_xor_sync(0xffffffffu, pl, 2);
        pl += __shfl_xor_sync(0xffffffffu, pl, 1);   // head logit
        float w = __expf(pl);
        den += w;
#pragma unroll
        for (int i = 0; i < 16; i++) acc[i] += w * v[i];
    }

    float inv = 1.f / den;
#pragma unroll
    for (int i = 0; i < 16; i++) {
        float a = acc[i] * inv;
        a += __shfl_xor_sync(0xffffffffu, a, 16);
        a += __shfl_xor_sync(0xffffffffu, a, 8);
        a += __shfl_xor_sync(0xffffffffu, a, 4);
        acc[i] = a;                        // head-sum, valid per q=lane&3
    }

    if (lane < 4) {                        // lanes 0..3 own channels q*16..q*16+15
        float v[16];
        const float4* bp = reinterpret_cast<const float4*>(bb + (size_t)layer * DD + lane * 16);
        const float4* xp = reinterpret_cast<const float4*>(xprev + (size_t)node * DD + lane * 16);
        float s1 = 0.f, s2 = 0.f;
#pragma unroll
        for (int i = 0; i < 4; i++) {
            float4 bv = bp[i], xv = xp[i];
            v[4 * i + 0] = acc[4 * i + 0] * 0.125f + bv.x + xv.x;
            v[4 * i + 1] = acc[4 * i + 1] * 0.125f + bv.y + xv.y;
            v[4 * i + 2] = acc[4 * i + 2] * 0.125f + bv.z + xv.z;
            v[4 * i + 3] = acc[4 * i + 3] * 0.125f + bv.w + xv.w;
        }
#pragma unroll
        for (int i = 0; i < 16; i++) { s1 += v[i]; s2 += v[i] * v[i]; }
        s1 += __shfl_xor_sync(0xFu, s1, 2);
        s1 += __shfl_xor_sync(0xFu, s1, 1);
        s2 += __shfl_xor_sync(0xFu, s2, 2);
        s2 += __shfl_xor_sync(0xFu, s2, 1);
        float mean = s1 * (1.f / DD);
        float var  = s2 * (1.f / DD) - mean * mean;
        float rstd = rsqrtf(var + LN_EPS);
        const float4* gp = reinterpret_cast<const float4*>(gam + (size_t)layer * DD + lane * 16);
        const float4* ep = reinterpret_cast<const float4*>(bet + (size_t)layer * DD + lane * 16);
        float4* op = reinterpret_cast<float4*>(xnext + (size_t)node * DD + lane * 16);
#pragma unroll
        for (int i = 0; i < 4; i++) {
            float4 gv = gp[i], bv = ep[i], o;
            o.x = fmaxf((v[4 * i + 0] - mean) * rstd * gv.x + bv.x, 0.f);
            o.y = fmaxf((v[4 * i + 1] - mean) * rstd * gv.y + bv.y, 0.f);
            o.z = fmaxf((v[4 * i + 2] - mean) * rstd * gv.z + bv.z, 0.f);
            o.w = fmaxf((v[4 * i + 3] - mean) * rstd * gv.w + bv.w, 0.f);
            op[i] = o;
        }
    }
}

// ---------------- launch ---------------------------------------------------
extern "C" void kernel_launch(void* const* d_in, const int* in_sizes, int n_in,
                              void* d_out, int out_size) {
    const float* x   = (const float*)d_in[0];
    const float* Wl  = (const float*)d_in[1];
    const float* Wr  = (const float*)d_in[2];
    const float* att = (const float*)d_in[3];
    const float* b   = (const float*)d_in[4];
    const float* gam = (const float*)d_in[5];
    const float* bet = (const float*)d_in[6];
    const void*  ei  = (const void*)d_in[7];
    float* out = (float*)d_out;

    cudaFuncSetAttribute(mm_kernel, cudaFuncAttributeMaxDynamicSharedMemorySize, SM_BYTES);

    const float* xin[3]  = { x, g_xb, g_xa };
    float*       xout[3] = { g_xb, g_xa, out };

    dim3 mgrid(4, 2, PPART);
    dim3 wgrid(128, 2);

    // layer-0 prep + GEMM first (mm is launch #4, the profiled slot)
    xprep_kernel<<<(NN * DD + 255) / 256, 256>>>(xin[0]);      // 1
    wprep_kernel<<<wgrid, 256>>>(Wl, Wr, 0);                   // 2
    zero_detect_kernel<<<(NN + 255) / 256, 256>>>(ei);         // 3
    mm_kernel<<<mgrid, 256, SM_BYTES>>>();                     // 4 <- profiled
    count_kernel<<<(ET + 255) / 256, 256>>>(ei);               // 5
    scan1_kernel<<<NSB, 512>>>();                              // 6
    scan2_kernel<<<1, 128>>>();                                // 7
    scan3_kernel<<<NSB, 512>>>();                              // 8
    scatter_kernel<<<(ET + 255) / 256, 256>>>(ei);             // 9

    for (int l = 0; l < 3; l++) {
        if (l > 0) {
            xprep_kernel<<<(NN * DD + 255) / 256, 256>>>(xin[l]);
            wprep_kernel<<<wgrid, 256>>>(Wl, Wr, l);
            mm_kernel<<<mgrid, 256, SM_BYTES>>>();
        }
        edge_node_kernel<<<NN / 8, 256>>>(att, b, gam, bet, xin[l], xout[l], l);
    }
}